// round 1
// baseline (speedup 1.0000x reference)
#include <cuda_runtime.h>
#include <math.h>

#define B_ 4
#define C_ 192
#define H_ 192
#define W_ 192
#define HW_ (H_*W_)
#define HEADS 6

// ---------------- scratch (device globals: allocation-free per harness rules) ----
__device__ float g_kv [(size_t)B_*2*C_*HW_];   // after 1x1 conv      (226 MB)
__device__ float g_kvd[(size_t)B_*2*C_*HW_];   // after depthwise: [k | v]
__device__ float g_q  [(size_t)B_*C_*HW_];     // q conv output       (113 MB)
__device__ float g_invq[B_*C_];
__device__ float g_invk[B_*C_];
__device__ float g_gram[B_*HEADS*32*32];
__device__ float g_weff[(size_t)B_*C_*C_];     // proj_w @ blockdiag(attn), per batch

// ---------------- generic tiled SGEMM: Y[b] = A[b] (MxK) * X[b] (K x HW_) --------
// BM=BN=64, BK=16, 256 threads, 4x4 per-thread tile. N stride hardwired to HW_.
__global__ __launch_bounds__(256) void gemm64(
    const float* __restrict__ A, size_t aStride,
    const float* __restrict__ X, size_t xStride,
    float* __restrict__ Y, size_t yStride, int K)
{
    __shared__ float sA[16][68];
    __shared__ float sB[16][68];
    int tid = threadIdx.x;
    int n0 = blockIdx.x * 64;
    int m0 = blockIdx.y * 64;
    const float* Ab = A + (size_t)blockIdx.z * aStride;
    const float* Xb = X + (size_t)blockIdx.z * xStride;
    float*       Yb = Y + (size_t)blockIdx.z * yStride;
    int ty = tid >> 4, tx = tid & 15;
    int ar  = tid >> 2;           // 0..63 (A row within tile)
    int akq = (tid & 3) << 2;     // 0,4,8,12 (A k quad)
    int xk  = tid >> 4;           // 0..15  (X k row)
    int xn  = (tid & 15) << 2;    // 0..60  (X n quad)
    float acc[4][4] = {};
    for (int k0 = 0; k0 < K; k0 += 16) {
        float4 av = *reinterpret_cast<const float4*>(&Ab[(size_t)(m0 + ar)*K + k0 + akq]);
        float4 xv = *reinterpret_cast<const float4*>(&Xb[(size_t)(k0 + xk)*HW_ + n0 + xn]);
        sA[akq+0][ar] = av.x; sA[akq+1][ar] = av.y;
        sA[akq+2][ar] = av.z; sA[akq+3][ar] = av.w;
        *reinterpret_cast<float4*>(&sB[xk][xn]) = xv;
        __syncthreads();
        #pragma unroll
        for (int kk = 0; kk < 16; kk++) {
            float4 a  = *reinterpret_cast<const float4*>(&sA[kk][ty<<2]);
            float4 bb = *reinterpret_cast<const float4*>(&sB[kk][tx<<2]);
            float aa[4] = {a.x, a.y, a.z, a.w};
            float bv[4] = {bb.x, bb.y, bb.z, bb.w};
            #pragma unroll
            for (int i = 0; i < 4; i++)
                #pragma unroll
                for (int j = 0; j < 4; j++)
                    acc[i][j] += aa[i] * bv[j];
        }
        __syncthreads();
    }
    #pragma unroll
    for (int i = 0; i < 4; i++) {
        float4 o = make_float4(acc[i][0], acc[i][1], acc[i][2], acc[i][3]);
        *reinterpret_cast<float4*>(
            &Yb[(size_t)(m0 + (ty<<2) + i)*HW_ + n0 + (tx<<2)]) = o;
    }
}

// ---------------- 3x3 dense conv (SAME): q = q_w * x --------------------------
// block = 64 out-channels x 64 x-pixels (one row segment); ic chunks of 8.
__global__ __launch_bounds__(256) void conv3x3(
    const float* __restrict__ x, const float* __restrict__ w, float* __restrict__ y)
{
    const int tilesX = W_ / 64;                 // 3
    int yrow = blockIdx.x / tilesX;
    int x0   = (blockIdx.x % tilesX) * 64;
    int oc0  = blockIdx.y * 64;
    int b    = blockIdx.z;
    __shared__ float sW[8][9][64];
    __shared__ float sX[8][3][72];
    int tid = threadIdx.x;
    int ty = tid >> 4, tx = tid & 15;
    float acc[4][4] = {};
    for (int ic0 = 0; ic0 < C_; ic0 += 8) {
        // weights: 64 oc x 8 ic x 9 taps
        for (int l = tid; l < 64*8*9; l += 256) {
            int oc  = l / 72;
            int rem = l % 72;
            sW[rem/9][rem%9][oc] = w[(size_t)(oc0+oc)*(C_*9) + ic0*9 + rem];
        }
        // input halo: 8 ic x 3 rows x 66 px
        for (int l = tid; l < 8*3*66; l += 256) {
            int ic  = l / 198;
            int rem = l - ic*198;
            int dy  = rem / 66;
            int xi  = rem - dy*66;
            int gy  = yrow + dy - 1;
            int gx  = x0 + xi - 1;
            float v = 0.f;
            if (gy >= 0 && gy < H_ && (unsigned)gx < (unsigned)W_)
                v = x[((size_t)(b*C_ + ic0+ic)*H_ + gy)*W_ + gx];
            sX[ic][dy][xi] = v;
        }
        __syncthreads();
        for (int ic = 0; ic < 8; ic++) {
            #pragma unroll
            for (int ky = 0; ky < 3; ky++) {
                float xs[6];
                #pragma unroll
                for (int t = 0; t < 6; t++) xs[t] = sX[ic][ky][(tx<<2) + t];
                #pragma unroll
                for (int kx = 0; kx < 3; kx++) {
                    float wv[4];
                    #pragma unroll
                    for (int i = 0; i < 4; i++) wv[i] = sW[ic][ky*3+kx][(ty<<2)+i];
                    #pragma unroll
                    for (int i = 0; i < 4; i++)
                        #pragma unroll
                        for (int j = 0; j < 4; j++)
                            acc[i][j] += wv[i] * xs[j+kx];
                }
            }
        }
        __syncthreads();
    }
    #pragma unroll
    for (int i = 0; i < 4; i++) {
        float4 o = make_float4(acc[i][0], acc[i][1], acc[i][2], acc[i][3]);
        *reinterpret_cast<float4*>(
            &y[((size_t)(b*C_ + oc0 + (ty<<2) + i)*H_ + yrow)*W_ + x0 + (tx<<2)]) = o;
    }
}

// ---------------- depthwise 3x3 (SAME), groups = 2C ---------------------------
__global__ void dwconv3x3(const float* __restrict__ in, const float* __restrict__ w,
                          float* __restrict__ out)
{
    size_t idx = (size_t)blockIdx.x * 256 + threadIdx.x;
    const size_t total = (size_t)B_*2*C_*HW_;
    if (idx >= total) return;
    int n  = (int)(idx % HW_);
    int ch = (int)((idx / HW_) % (2*C_));
    int px = n % W_, py = n / W_;
    const float* base = in + (idx - n);
    float s = 0.f;
    #pragma unroll
    for (int ky = 0; ky < 3; ky++) {
        int gy = py + ky - 1;
        if ((unsigned)gy >= (unsigned)H_) continue;
        #pragma unroll
        for (int kx = 0; kx < 3; kx++) {
            int gx = px + kx - 1;
            if ((unsigned)gx >= (unsigned)W_) continue;
            s += w[ch*9 + ky*3 + kx] * base[(size_t)gy*W_ + gx];
        }
    }
    out[idx] = s;
}

// ---------------- 1/max(||row||,eps) over HW per (b,c) ------------------------
__global__ __launch_bounds__(256) void invnorm(const float* __restrict__ src,
                                               int chanPerB, float* __restrict__ dst)
{
    int bc = blockIdx.x;
    int b = bc / C_, c = bc % C_;
    const float4* p = reinterpret_cast<const float4*>(src + ((size_t)b*chanPerB + c)*HW_);
    float ss = 0.f;
    for (int i = threadIdx.x; i < HW_/4; i += 256) {
        float4 v = p[i];
        ss += v.x*v.x + v.y*v.y + v.z*v.z + v.w*v.w;
    }
    #pragma unroll
    for (int off = 16; off; off >>= 1) ss += __shfl_xor_sync(0xffffffff, ss, off);
    __shared__ float red[8];
    if ((threadIdx.x & 31) == 0) red[threadIdx.x >> 5] = ss;
    __syncthreads();
    if (threadIdx.x == 0) {
        float t = 0.f;
        #pragma unroll
        for (int i = 0; i < 8; i++) t += red[i];
        float nrm = sqrtf(t);
        dst[bc] = 1.f / fmaxf(nrm, 1e-12f);
    }
}

__global__ void zero_gram()
{
    int i = blockIdx.x * 256 + threadIdx.x;
    if (i < B_*HEADS*32*32) g_gram[i] = 0.f;
}

// ---------------- 32x32 Gram per (b,h), N split 8 ways, atomic accumulate -----
__global__ __launch_bounds__(256) void gram_kernel(const float* __restrict__ q,
                                                   const float* __restrict__ kk)
{
    int split = blockIdx.x;              // 0..7
    int bh = blockIdx.y;                 // 0..23
    int b = bh / HEADS, h = bh % HEADS;
    __shared__ float qs[32][65], ks[32][65];
    const float* qb = q  + ((size_t)b*C_   + h*32)*HW_;
    const float* kb = kk + ((size_t)b*2*C_ + h*32)*HW_;
    int n0 = split * (HW_/8);
    int tid = threadIdx.x;
    int c = tid >> 3, d0 = (tid & 7) << 2;
    float acc[4] = {0.f, 0.f, 0.f, 0.f};
    for (int nt = 0; nt < HW_/8; nt += 64) {
        for (int l = tid; l < 2048; l += 256) {
            int cc = l >> 6, nn = l & 63;
            size_t off = (size_t)cc*HW_ + n0 + nt + nn;
            qs[cc][nn] = qb[off];
            ks[cc][nn] = kb[off];
        }
        __syncthreads();
        #pragma unroll 8
        for (int n = 0; n < 64; n++) {
            float qv = qs[c][n];
            #pragma unroll
            for (int j = 0; j < 4; j++) acc[j] += qv * ks[d0+j][n];
        }
        __syncthreads();
    }
    #pragma unroll
    for (int j = 0; j < 4; j++)
        atomicAdd(&g_gram[((size_t)bh*32 + c)*32 + d0 + j], acc[j]);
}

// ---------------- scale + softmax + fold with proj_w --> W_eff ---------------
// W_eff[b][co][h*32+d] = sum_c proj[co][h*32+c] * attn[b,h,c,d]
__global__ __launch_bounds__(256) void softfold(const float* __restrict__ temp,
                                                const float* __restrict__ proj)
{
    int bh = blockIdx.x;
    int b = bh / HEADS, h = bh % HEADS;
    __shared__ float attn[32][33];
    int tid = threadIdx.x;
    int wrp = tid >> 5, ln = tid & 31;
    float tmp = temp[h];
    for (int r = wrp; r < 32; r += 8) {
        float v = g_gram[((size_t)bh*32 + r)*32 + ln]
                * g_invq[b*C_ + h*32 + r] * g_invk[b*C_ + h*32 + ln] * tmp;
        float m = v;
        #pragma unroll
        for (int off = 16; off; off >>= 1) m = fmaxf(m, __shfl_xor_sync(0xffffffff, m, off));
        float e = expf(v - m);
        float s = e;
        #pragma unroll
        for (int off = 16; off; off >>= 1) s += __shfl_xor_sync(0xffffffff, s, off);
        attn[r][ln] = e / s;
    }
    __syncthreads();
    for (int l = tid; l < C_*32; l += 256) {
        int co = l >> 5, d = l & 31;
        float s = 0.f;
        #pragma unroll
        for (int cc = 0; cc < 32; cc++)
            s += proj[(size_t)co*C_ + h*32 + cc] * attn[cc][d];
        g_weff[((size_t)b*C_ + co)*C_ + h*32 + d] = s;
    }
}

// ---------------- launcher ----------------------------------------------------
extern "C" void kernel_launch(void* const* d_in, const int* in_sizes, int n_in,
                              void* d_out, int out_size)
{
    const float* x           = (const float*)d_in[0];
    const float* y           = (const float*)d_in[1];
    const float* q_w         = (const float*)d_in[2];
    const float* kv_w        = (const float*)d_in[3];
    const float* kvdw_w      = (const float*)d_in[4];
    const float* proj_w      = (const float*)d_in[5];
    const float* temperature = (const float*)d_in[6];

    float *p_kv, *p_kvd, *p_q, *p_invq, *p_invk, *p_weff;
    cudaGetSymbolAddress((void**)&p_kv,   g_kv);
    cudaGetSymbolAddress((void**)&p_kvd,  g_kvd);
    cudaGetSymbolAddress((void**)&p_q,    g_q);
    cudaGetSymbolAddress((void**)&p_invq, g_invq);
    cudaGetSymbolAddress((void**)&p_invk, g_invk);
    cudaGetSymbolAddress((void**)&p_weff, g_weff);

    // kv = kv_w (384x192) @ y   (1x1 conv as GEMM)
    gemm64<<<dim3(HW_/64, 384/64, B_), 256>>>(
        kv_w, 0, y, (size_t)C_*HW_, p_kv, (size_t)2*C_*HW_, C_);

    // depthwise 3x3 on kv -> [k | v]
    {
        size_t total = (size_t)B_*2*C_*HW_;
        dwconv3x3<<<(unsigned)((total + 255)/256), 256>>>(p_kv, kvdw_w, p_kvd);
    }

    // q = conv3x3(x, q_w)
    conv3x3<<<dim3(H_*(W_/64), C_/64, B_), 256>>>(x, q_w, p_q);

    // inverse L2 norms over HW per channel
    invnorm<<<B_*C_, 256>>>(p_q,   C_,   p_invq);
    invnorm<<<B_*C_, 256>>>(p_kvd, 2*C_, p_invk);

    // Gram(q,k) per (b,h), then softmax + fold proj -> W_eff
    zero_gram<<<(B_*HEADS*32*32 + 255)/256, 256>>>();
    gram_kernel<<<dim3(8, B_*HEADS), 256>>>(p_q, p_kvd);
    softfold<<<B_*HEADS, 256>>>(temperature, proj_w);

    // out = W_eff[b] (192x192) @ v[b]  (fuses attn@v and the 1x1 proj)
    gemm64<<<dim3(HW_/64, C_/64, B_), 256>>>(
        p_weff, (size_t)C_*C_, p_kvd + (size_t)C_*HW_, (size_t)2*C_*HW_,
        (float*)d_out, (size_t)C_*HW_, C_);
}